// round 14
// baseline (speedup 1.0000x reference)
#include <cuda_runtime.h>
#include <cuda_bf16.h>
#include <cuda_fp16.h>
#include <cstdint>

// ===========================================================================
// TGNN R14 — R9 structure; trunk switched to fp16 inputs + fp16 accumulators
// (tests whether legacy mma.sync f32-accum is half-rate on sm_103a).
//   prep_all    : fp16 trunk weights + bf16 batch weights + zeroing
//   embed_all   : fp32 pairs -> fp16 -> 3 embed GEMMs (f16 acc) -> h384 f16
//   tc_gemm_h   : p1, fp16/f16-acc, BK=64 double buffer (R9 pipeline)
//   fused_p2_segsum : p2 fp16/f16-acc + fp32 deterministic segment sums
//   batch: p3,f1 bf16 f32-acc (R9 v2); f2/final SIMT fp32
// ===========================================================================

#define P_MAX  200000
#define B_MAX  2000

__device__ __half g_h384[(size_t)P_MAX * 384];
__device__ __half g_h512[(size_t)P_MAX * 512];
__device__ float g_part[2 * (size_t)B_MAX * 256];
__device__ __nv_bfloat16 g_hm_bf[(size_t)B_MAX * 256];
__device__ __nv_bfloat16 g_y_bf [(size_t)B_MAX * 1024];
__device__ float g_z   [(size_t)B_MAX * 512];
__device__ float g_w   [(size_t)B_MAX * 32];
__device__ __half        g_wh [512 * 1024];    // fp16 trunk weights
__device__ __nv_bfloat16 g_wbf[1024 * 1024];   // bf16 batch weights

// ---------------------------------------------------------------------------
__device__ __forceinline__ uint32_t h2_bits(float lo, float hi) {
    __half2 p = __floats2half2_rn(lo, hi);
    return *reinterpret_cast<uint32_t*>(&p);
}
__device__ __forceinline__ void cp_async16(uint32_t smem_addr, const void* gptr, int src_bytes) {
    asm volatile("cp.async.ca.shared.global [%0], [%1], 16, %2;\n"
                 :: "r"(smem_addr), "l"(gptr), "r"(src_bytes));
}
#define CP_ASYNC_COMMIT() asm volatile("cp.async.commit_group;\n" ::: "memory")
#define CP_ASYNC_WAIT0()  asm volatile("cp.async.wait_group 0;\n" ::: "memory")

__device__ __forceinline__ uint32_t smem_u32(const void* p) {
    uint32_t a;
    asm("{ .reg .u64 t; cvta.to.shared.u64 t, %1; cvt.u32.u64 %0, t; }" : "=r"(a) : "l"(p));
    return a;
}
// f16 inputs, f16 accumulators (2 packed-half regs)
__device__ __forceinline__ void mma_f16(uint32_t& c0, uint32_t& c1,
                                        uint32_t a0, uint32_t a1, uint32_t a2, uint32_t a3,
                                        uint32_t b0, uint32_t b1) {
    asm volatile(
        "mma.sync.aligned.m16n8k16.row.col.f16.f16.f16.f16 "
        "{%0,%1}, {%2,%3,%4,%5}, {%6,%7}, {%0,%1};"
        : "+r"(c0), "+r"(c1)
        : "r"(a0), "r"(a1), "r"(a2), "r"(a3), "r"(b0), "r"(b1));
}
// bf16 inputs, f32 accumulators (batch layers, proven R9)
__device__ __forceinline__ void mma_bf16(float& c0, float& c1, float& c2, float& c3,
                                         uint32_t a0, uint32_t a1, uint32_t a2, uint32_t a3,
                                         uint32_t b0, uint32_t b1) {
    asm volatile(
        "mma.sync.aligned.m16n8k16.row.col.f32.bf16.bf16.f32 "
        "{%0,%1,%2,%3}, {%4,%5,%6,%7}, {%8,%9}, {%0,%1,%2,%3};"
        : "+f"(c0), "+f"(c1), "+f"(c2), "+f"(c3)
        : "r"(a0), "r"(a1), "r"(a2), "r"(a3), "r"(b0), "r"(b1));
}
__device__ __forceinline__ void ldsm_x4(uint32_t* r, uint32_t addr) {
    asm volatile("ldmatrix.sync.aligned.m8n8.x4.shared.b16 {%0,%1,%2,%3}, [%4];"
                 : "=r"(r[0]), "=r"(r[1]), "=r"(r[2]), "=r"(r[3]) : "r"(addr));
}

// ---------------------------------------------------------------------------
// Tile block = 128 rows x 32 k (16-bit); smem row = 64B data + 16B pad (80B).
// ---------------------------------------------------------------------------
#define TILE_B 10240

template <typename T>
__device__ __forceinline__ void load_tile(uint32_t dst, const T* __restrict__ src,
                                          int ld, int rbase, int rmax, int k0, int tid)
{
#pragma unroll
    for (int h = 0; h < 2; h++) {
        const int chunk = tid + h * 256;
        const int row = chunk >> 2;
        const int ck  = chunk & 3;
        const int gr  = rbase + row;
        const char* p = (const char*)(src + (size_t)gr * ld + k0 + ck * 8);
        cp_async16(dst + row * 80 + ck * 16, p, gr < rmax ? 16 : 0);
    }
}

// f16-accumulator ldmatrix k32 block (R8 address mapping, packed-half acc)
__device__ __forceinline__ void mma_block_h(uint32_t Abase, uint32_t Bbase,
                                            uint32_t acc[2][8][2],
                                            int lane, int warp_m, int warp_n)
{
    const int l7  = lane & 7;
    const int lb3 = (lane >> 3) & 1;
    const int lb4 = lane >> 4;
#pragma unroll
    for (int ks = 0; ks < 2; ks++) {
        uint32_t a[2][4];
#pragma unroll
        for (int mt = 0; mt < 2; mt++) {
            uint32_t addr = Abase + (uint32_t)(warp_m + mt * 16 + lb3 * 8 + l7) * 80
                          + ks * 32 + lb4 * 16;
            ldsm_x4(a[mt], addr);
        }
        uint32_t b[8][2];
#pragma unroll
        for (int np = 0; np < 4; np++) {
            uint32_t r[4];
            uint32_t addr = Bbase + (uint32_t)(warp_n + np * 16 + lb4 * 8 + l7) * 80
                          + ks * 32 + lb3 * 16;
            ldsm_x4(r, addr);
            b[2 * np][0]     = r[0];
            b[2 * np][1]     = r[1];
            b[2 * np + 1][0] = r[2];
            b[2 * np + 1][1] = r[3];
        }
#pragma unroll
        for (int mt = 0; mt < 2; mt++)
#pragma unroll
            for (int nt = 0; nt < 8; nt++)
                mma_f16(acc[mt][nt][0], acc[mt][nt][1],
                        a[mt][0], a[mt][1], a[mt][2], a[mt][3],
                        b[nt][0], b[nt][1]);
    }
}

// bf16 f32-acc block (batch layers, proven R9)
__device__ __forceinline__ void mma_block_ldsm(uint32_t Abase, uint32_t Bbase,
                                               float acc[2][8][4],
                                               int lane, int warp_m, int warp_n)
{
    const int l7  = lane & 7;
    const int lb3 = (lane >> 3) & 1;
    const int lb4 = lane >> 4;
#pragma unroll
    for (int ks = 0; ks < 2; ks++) {
        uint32_t a[2][4];
#pragma unroll
        for (int mt = 0; mt < 2; mt++) {
            uint32_t addr = Abase + (uint32_t)(warp_m + mt * 16 + lb3 * 8 + l7) * 80
                          + ks * 32 + lb4 * 16;
            ldsm_x4(a[mt], addr);
        }
        uint32_t b[8][2];
#pragma unroll
        for (int np = 0; np < 4; np++) {
            uint32_t r[4];
            uint32_t addr = Bbase + (uint32_t)(warp_n + np * 16 + lb4 * 8 + l7) * 80
                          + ks * 32 + lb3 * 16;
            ldsm_x4(r, addr);
            b[2 * np][0]     = r[0];
            b[2 * np][1]     = r[1];
            b[2 * np + 1][0] = r[2];
            b[2 * np + 1][1] = r[3];
        }
#pragma unroll
        for (int mt = 0; mt < 2; mt++)
#pragma unroll
            for (int nt = 0; nt < 8; nt++)
                mma_bf16(acc[mt][nt][0], acc[mt][nt][1], acc[mt][nt][2], acc[mt][nt][3],
                         a[mt][0], a[mt][1], a[mt][2], a[mt][3],
                         b[nt][0], b[nt][1]);
    }
}

// ===========================================================================
// embed_all: fp16 trunk version of the proven R8 kernel.
// ===========================================================================
#define SMEM_EA (5 * TILE_B + 3 * TILE_B)

__global__ __launch_bounds__(256)
void embed_all(const float* __restrict__ pairs,
               const __half* __restrict__ awt,
               const __half* __restrict__ bwt,
               const float* __restrict__ ab, const float* __restrict__ bb,
               __half* __restrict__ h384, int P)
{
    extern __shared__ char smem[];
    const uint32_t smem_base = smem_u32(smem);

    const int tid = threadIdx.x;
    const int wid = tid >> 5, lane = tid & 31;
    const int g = lane >> 2, t = lane & 3;
    const int warp_m = (wid & 3) * 32;
    const int warp_n = (wid >> 2) * 64;
    const int blockRow = blockIdx.x * 128;

    load_tile(smem_base + 5 * TILE_B,          awt, 64, 0, 1 << 30, 0,  tid);
    load_tile(smem_base + 5 * TILE_B + TILE_B, awt, 64, 0, 1 << 30, 32, tid);
    load_tile(smem_base + 7 * TILE_B,          bwt, 32, 0, 1 << 30, 0,  tid);
    CP_ASYNC_COMMIT();

    {
        const int r = tid >> 1;
        const int h = tid & 1;
        const int gr = blockRow + r;
        const bool ok = (gr < P);
        const float* rp = pairs + (size_t)gr * 160 + h * 80;
#pragma unroll
        for (int i = 0; i < 20; i++) {
            float4 v = ok ? *reinterpret_cast<const float4*>(rp + i * 4)
                          : make_float4(0.f, 0.f, 0.f, 0.f);
            const int col = h * 80 + i * 4;
            const int kb = col >> 5, kin = col & 31;
            uint2 pk;
            pk.x = h2_bits(v.x, v.y);
            pk.y = h2_bits(v.z, v.w);
            *reinterpret_cast<uint2*>(smem + kb * TILE_B + r * 80 + kin * 2) = pk;
        }
    }
    CP_ASYNC_WAIT0();
    __syncthreads();

    uint32_t acc[2][8][2];
#pragma unroll
    for (int c = 0; c < 3; c++) {
        const int nkb = (c < 2) ? 2 : 1;
        const int ab0 = c * 2;
        const uint32_t woff = (c < 2) ? 5 * TILE_B : 7 * TILE_B;
        const float* biasc = (c < 2) ? ab : bb;

#pragma unroll
        for (int mt = 0; mt < 2; mt++)
#pragma unroll
            for (int nt = 0; nt < 8; nt++) { acc[mt][nt][0] = 0; acc[mt][nt][1] = 0; }

        for (int kb = 0; kb < nkb; kb++)
            mma_block_h(smem_base + (ab0 + kb) * TILE_B,
                        smem_base + woff + kb * TILE_B,
                        acc, lane, warp_m, warp_n);

#pragma unroll
        for (int nt = 0; nt < 8; nt++) {
            const int col = warp_n + nt * 8 + 2 * t;
            const float2 bv = *(const float2*)&biasc[col];
#pragma unroll
            for (int mt = 0; mt < 2; mt++)
#pragma unroll
                for (int half = 0; half < 2; half++) {
                    const int row = blockRow + warp_m + mt * 16 + half * 8 + g;
                    if (row >= P) continue;
                    float2 cv = __half22float2(*reinterpret_cast<__half2*>(&acc[mt][nt][half]));
                    float v0 = fmaxf(cv.x + bv.x, 0.f);
                    float v1 = fmaxf(cv.y + bv.y, 0.f);
                    *(__half2*)(h384 + (size_t)row * 384 + c * 128 + col) =
                        __floats2half2_rn(v0, v1);
                }
        }
    }
}

// ===========================================================================
// tc_gemm_h: fp16/f16-acc trunk GEMM (p1). R9 v2 pipeline: BK=64, 2-stage.
// ===========================================================================
#define STAGE64  (4 * TILE_B)
#define SMEM_V2  (2 * STAGE64)

__global__ __launch_bounds__(256)
void tc_gemm_h(const __half* __restrict__ A, int lda,
               const __half* __restrict__ WT,
               const float* __restrict__ bias,
               __half* __restrict__ C, int ldc,
               int M, int K)
{
    extern __shared__ char smem[];
    const uint32_t smem_base = smem_u32(smem);

    const int tid  = threadIdx.x;
    const int wid  = tid >> 5, lane = tid & 31;
    const int g    = lane >> 2, t = lane & 3;

    const int blockRow = blockIdx.x * 128;
    const int blockCol = blockIdx.y * 128;
    const int warp_m = (wid & 3) * 32;
    const int warp_n = (wid >> 2) * 64;

    const int NIT = K >> 6;

    uint32_t acc[2][8][2];
#pragma unroll
    for (int mt = 0; mt < 2; mt++)
#pragma unroll
        for (int nt = 0; nt < 8; nt++) { acc[mt][nt][0] = 0; acc[mt][nt][1] = 0; }

    auto load_stage = [&](int it) {
        const uint32_t base = smem_base + (it & 1) * STAGE64;
        const int k0 = it * 64;
        load_tile(base,              A,  lda, blockRow, M,       k0,      tid);
        load_tile(base + TILE_B,     A,  lda, blockRow, M,       k0 + 32, tid);
        load_tile(base + 2 * TILE_B, WT, K,   blockCol, 1 << 30, k0,      tid);
        load_tile(base + 3 * TILE_B, WT, K,   blockCol, 1 << 30, k0 + 32, tid);
        CP_ASYNC_COMMIT();
    };

    load_stage(0);

    for (int it = 0; it < NIT; it++) {
        CP_ASYNC_WAIT0();
        __syncthreads();
        if (it + 1 < NIT) load_stage(it + 1);
        const uint32_t base = smem_base + (it & 1) * STAGE64;
        mma_block_h(base,          base + 2 * TILE_B, acc, lane, warp_m, warp_n);
        mma_block_h(base + TILE_B, base + 3 * TILE_B, acc, lane, warp_m, warp_n);
    }

#pragma unroll
    for (int nt = 0; nt < 8; nt++) {
        const int col = blockCol + warp_n + nt * 8 + 2 * t;
        const float2 bv = *reinterpret_cast<const float2*>(&bias[col]);
#pragma unroll
        for (int mt = 0; mt < 2; mt++)
#pragma unroll
            for (int half = 0; half < 2; half++) {
                const int row = blockRow + warp_m + mt * 16 + half * 8 + g;
                if (row >= M) continue;
                float2 cv = __half22float2(*reinterpret_cast<__half2*>(&acc[mt][nt][half]));
                float v0 = fmaxf(cv.x + bv.x, 0.f);
                float v1 = fmaxf(cv.y + bv.y, 0.f);
                *(__half2*)(C + (size_t)row * ldc + col) = __floats2half2_rn(v0, v1);
            }
    }
}

// ===========================================================================
// fused_p2_segsum: fp16/f16-acc p2 + fp32 deterministic segment sums.
// ===========================================================================
#define REDPAD 129
#define SMEM_P2 (2 * STAGE64)   // 81920 >= 128*129*4

__global__ __launch_bounds__(256)
void fused_p2_segsum(const __half* __restrict__ h512,
                     const __half* __restrict__ p2t,
                     const float* __restrict__ p2b,
                     float* __restrict__ part, int P, int group, int Bseg)
{
    extern __shared__ char smem[];
    const uint32_t smem_base = smem_u32(smem);
    float* red = (float*)smem;

    const int tid = threadIdx.x;
    const int wid = tid >> 5, lane = tid & 31;
    const int g = lane >> 2, t = lane & 3;
    const int warp_m = (wid & 3) * 32;
    const int warp_n = (wid >> 2) * 64;
    const int blockRow = blockIdx.x * 128;

    uint32_t acc[2][8][2];

    for (int nc = 0; nc < 2; nc++) {
#pragma unroll
        for (int mt = 0; mt < 2; mt++)
#pragma unroll
            for (int nt = 0; nt < 8; nt++) { acc[mt][nt][0] = 0; acc[mt][nt][1] = 0; }

        auto load_stage = [&](int it) {
            const uint32_t base = smem_base + (it & 1) * STAGE64;
            const int k0 = it * 64;
            load_tile(base,              h512, 512, blockRow, P,       k0,      tid);
            load_tile(base + TILE_B,     h512, 512, blockRow, P,       k0 + 32, tid);
            load_tile(base + 2 * TILE_B, p2t,  512, nc * 128, 1 << 30, k0,      tid);
            load_tile(base + 3 * TILE_B, p2t,  512, nc * 128, 1 << 30, k0 + 32, tid);
            CP_ASYNC_COMMIT();
        };

        load_stage(0);
        for (int it = 0; it < 8; it++) {          // K=512 -> 8 blocks of 64
            CP_ASYNC_WAIT0();
            __syncthreads();
            if (it + 1 < 8) load_stage(it + 1);
            const uint32_t base = smem_base + (it & 1) * STAGE64;
            mma_block_h(base,          base + 2 * TILE_B, acc, lane, warp_m, warp_n);
            mma_block_h(base + TILE_B, base + 3 * TILE_B, acc, lane, warp_m, warp_n);
        }
        __syncthreads();   // drain before red aliases the stages

#pragma unroll
        for (int nt = 0; nt < 8; nt++) {
            const int col = warp_n + nt * 8 + 2 * t;
            const float2 bv = *(const float2*)&p2b[nc * 128 + col];
#pragma unroll
            for (int mt = 0; mt < 2; mt++)
#pragma unroll
                for (int half = 0; half < 2; half++) {
                    const int row = warp_m + mt * 16 + half * 8 + g;
                    float2 cv = __half22float2(*reinterpret_cast<__half2*>(&acc[mt][nt][half]));
                    red[row * REDPAD + col]     = fmaxf(cv.x + bv.x, 0.f);
                    red[row * REDPAD + col + 1] = fmaxf(cv.y + bv.y, 0.f);
                }
        }
        __syncthreads();

        {
            const int col = tid & 127;
            const int rb  = (tid >> 7) * 64;
            float s = 0.f;
            bool any = false;
            int curseg = 0, nxt = 0;
            for (int r = rb; r < rb + 64; r++) {
                const int grow = blockRow + r;
                if (grow >= P) break;
                if (!any) {
                    curseg = grow / group;
                    nxt = (curseg + 1) * group;
                    any = true;
                } else if (grow >= nxt) {
                    const int slot = blockIdx.x - (curseg * group) / 128;
                    atomicAdd(&part[(size_t)slot * Bseg * 256 + curseg * 256 + nc * 128 + col], s);
                    s = 0.f;
                    curseg++;
                    nxt += group;
                }
                s += red[r * REDPAD + col];
            }
            if (any) {
                const int slot = blockIdx.x - (curseg * group) / 128;
                atomicAdd(&part[(size_t)slot * Bseg * 256 + curseg * 256 + nc * 128 + col], s);
            }
        }
        __syncthreads();
    }
}

// ===========================================================================
// tc_gemm_v2 (proven R9, bf16 f32-acc): batch layers p3, f1.
// ===========================================================================
__global__ __launch_bounds__(256)
void tc_gemm_v2(const __nv_bfloat16* __restrict__ A, int lda,
                const __nv_bfloat16* __restrict__ WT,
                const float* __restrict__ bias,
                void* __restrict__ Cv, int ldc,
                int M, int K, int relu, int out_bf16)
{
    extern __shared__ char smem[];
    const uint32_t smem_base = smem_u32(smem);

    const int tid  = threadIdx.x;
    const int wid  = tid >> 5, lane = tid & 31;
    const int g    = lane >> 2, t = lane & 3;

    const int blockRow = blockIdx.x * 128;
    const int blockCol = blockIdx.y * 128;
    const int warp_m = (wid & 3) * 32;
    const int warp_n = (wid >> 2) * 64;

    const int NIT = K >> 6;

    float acc[2][8][4];
#pragma unroll
    for (int mt = 0; mt < 2; mt++)
#pragma unroll
        for (int nt = 0; nt < 8; nt++)
#pragma unroll
            for (int i = 0; i < 4; i++) acc[mt][nt][i] = 0.0f;

    auto load_stage = [&](int it) {
        const uint32_t base = smem_base + (it & 1) * STAGE64;
        const int k0 = it * 64;
        load_tile(base,              A,  lda, blockRow, M,       k0,      tid);
        load_tile(base + TILE_B,     A,  lda, blockRow, M,       k0 + 32, tid);
        load_tile(base + 2 * TILE_B, WT, K,   blockCol, 1 << 30, k0,      tid);
        load_tile(base + 3 * TILE_B, WT, K,   blockCol, 1 << 30, k0 + 32, tid);
        CP_ASYNC_COMMIT();
    };

    load_stage(0);

    for (int it = 0; it < NIT; it++) {
        CP_ASYNC_WAIT0();
        __syncthreads();
        if (it + 1 < NIT) load_stage(it + 1);
        const uint32_t base = smem_base + (it & 1) * STAGE64;
        mma_block_ldsm(base,          base + 2 * TILE_B, acc, lane, warp_m, warp_n);
        mma_block_ldsm(base + TILE_B, base + 3 * TILE_B, acc, lane, warp_m, warp_n);
    }

#pragma unroll
    for (int nt = 0; nt < 8; nt++) {
        const int col = blockCol + warp_n + nt * 8 + 2 * t;
        const float2 bv = *reinterpret_cast<const float2*>(&bias[col]);
#pragma unroll
        for (int mt = 0; mt < 2; mt++)
#pragma unroll
            for (int half = 0; half < 2; half++) {
                const int row = blockRow + warp_m + mt * 16 + half * 8 + g;
                if (row >= M) continue;
                float v0 = acc[mt][nt][half * 2 + 0] + bv.x;
                float v1 = acc[mt][nt][half * 2 + 1] + bv.y;
                if (relu) { v0 = fmaxf(v0, 0.f); v1 = fmaxf(v1, 0.f); }
                if (out_bf16) {
                    *(__nv_bfloat162*)((__nv_bfloat16*)Cv + (size_t)row * ldc + col) =
                        __float22bfloat162_rn(make_float2(v0, v1));
                } else {
                    *reinterpret_cast<float2*>((float*)Cv + (size_t)row * ldc + col) =
                        make_float2(v0, v1);
                }
            }
    }
}

// ===========================================================================
// prep_all: fp16 trunk weights, bf16 batch weights, zero partials.
// ===========================================================================
#define AWT_SZ  (128 * 64)
#define BWT_SZ  (128 * 32)
#define P1T_SZ  (512 * 384)
#define P2T_SZ  (256 * 512)
#define P3T_SZ  (1024 * 256)
#define F1T_SZ  (512 * 1024)
#define ZERO_SZ (2 * B_MAX * 256)
#define FP16_TOTAL (AWT_SZ + BWT_SZ + P1T_SZ + P2T_SZ)
#define PREP_TOTAL (FP16_TOTAL + P3T_SZ + F1T_SZ + ZERO_SZ)

__global__ void prep_all(const float* __restrict__ aw,  const float* __restrict__ bw,
                         const float* __restrict__ p1w, const float* __restrict__ p2w,
                         const float* __restrict__ p3w, const float* __restrict__ f1w,
                         __half* __restrict__ wh, __nv_bfloat16* __restrict__ wbf,
                         float* __restrict__ part)
{
    int i = blockIdx.x * blockDim.x + threadIdx.x;
    if (i >= PREP_TOTAL) return;
    int off = 0;
    if (i < off + AWT_SZ) {
        int j = i - off; int n = j / 64, k = j % 64;
        wh[i] = __float2half(aw[(size_t)k * 128 + n]); return;
    } off += AWT_SZ;
    if (i < off + BWT_SZ) {
        int j = i - off; int n = j / 32, k = j % 32;
        wh[i] = __float2half(bw[(size_t)k * 128 + n]); return;
    } off += BWT_SZ;
    if (i < off + P1T_SZ) {
        int j = i - off; int n = j / 384, k = j % 384;
        wh[i] = __float2half(p1w[(size_t)k * 512 + n]); return;
    } off += P1T_SZ;
    if (i < off + P2T_SZ) {
        int j = i - off; int n = j / 512, k = j % 512;
        wh[i] = __float2half(p2w[(size_t)k * 256 + n]); return;
    } off += P2T_SZ;
    if (i < off + P3T_SZ) {
        int j = i - off; int n = j / 256, k = j % 256;
        wbf[j] = __float2bfloat16(p3w[(size_t)k * 1024 + n]); return;
    } off += P3T_SZ;
    if (i < off + F1T_SZ) {
        int j = i - off; int n = j / 1024, k = j % 1024;
        wbf[P3T_SZ + j] = __float2bfloat16(f1w[(size_t)k * 512 + n]); return;
    } off += F1T_SZ;
    part[i - off] = 0.0f;
}

// ---------------------------------------------------------------------------
__global__ void hm_combine(const float* __restrict__ part, const int* __restrict__ idx,
                           __nv_bfloat16* __restrict__ hm, int Bseg)
{
    int i = blockIdx.x * blockDim.x + threadIdx.x;
    if (i >= Bseg * 256) return;
    int s = i >> 8;
    hm[i] = __float2bfloat16((part[i] + part[(size_t)Bseg * 256 + i]) / (float)idx[s]);
}

// ---------------------------------------------------------------------------
__global__ __launch_bounds__(256, 2)
void gemm_simt(const float* __restrict__ A, int lda,
               const float* __restrict__ W, int ldw,
               const float* __restrict__ bias,
               float* __restrict__ C, int ldc,
               int M, int N, int K, int relu)
{
    int gm = blockIdx.x * 64 + (threadIdx.x >> 2);
    int nq = (threadIdx.x & 3) * 8;
    if (gm >= M) return;
    float acc[8] = {0,0,0,0,0,0,0,0};
    const float* a = A + (size_t)gm * lda;
    for (int k = 0; k < K; k++) {
        float av = a[k];
        const float* wr = W + (size_t)k * ldw + nq;
#pragma unroll
        for (int j = 0; j < 8; j++) acc[j] = fmaf(av, wr[j], acc[j]);
    }
#pragma unroll
    for (int j = 0; j < 8; j++) {
        float v = acc[j] + bias[nq + j];
        if (relu) v = fmaxf(v, 0.0f);
        C[(size_t)gm * ldc + nq + j] = v;
    }
}

__global__ void final_kernel(const float* __restrict__ w,
                             const float* __restrict__ f3w,
                             const float* __restrict__ f3b,
                             float* __restrict__ out, int B)
{
    const int r = blockIdx.x * blockDim.x + threadIdx.x;
    if (r >= B) return;
    float s = 0.0f;
#pragma unroll
    for (int k = 0; k < 32; k++) s = fmaf(w[(size_t)r * 32 + k], f3w[k], s);
    out[r] = s + f3b[0];
}

// ---------------------------------------------------------------------------
extern "C" void kernel_launch(void* const* d_in, const int* in_sizes, int n_in,
                              void* d_out, int out_size)
{
    const float* pairs     = (const float*)d_in[0];
    const int*   idx_pairs = (const int*)  d_in[1];
    const float* aw  = (const float*)d_in[3];
    const float* ab  = (const float*)d_in[4];
    const float* bw  = (const float*)d_in[5];
    const float* bb  = (const float*)d_in[6];
    const float* p1w = (const float*)d_in[7];
    const float* p1b = (const float*)d_in[8];
    const float* p2w = (const float*)d_in[9];
    const float* p2b = (const float*)d_in[10];
    const float* p3w = (const float*)d_in[11];
    const float* p3b = (const float*)d_in[12];
    const float* f1w = (const float*)d_in[13];
    const float* f1b = (const float*)d_in[14];
    const float* f2w = (const float*)d_in[15];
    const float* f2b = (const float*)d_in[16];
    const float* f3w = (const float*)d_in[17];
    const float* f3b = (const float*)d_in[18];
    float* out = (float*)d_out;

    const int P = in_sizes[0] / 160;
    const int B = in_sizes[1];
    const int group = P / B;

    cudaFuncSetAttribute(embed_all,       cudaFuncAttributeMaxDynamicSharedMemorySize, SMEM_EA);
    cudaFuncSetAttribute(tc_gemm_h,       cudaFuncAttributeMaxDynamicSharedMemorySize, SMEM_V2);
    cudaFuncSetAttribute(tc_gemm_v2,      cudaFuncAttributeMaxDynamicSharedMemorySize, SMEM_V2);
    cudaFuncSetAttribute(fused_p2_segsum, cudaFuncAttributeMaxDynamicSharedMemorySize, SMEM_P2);

    __half *h384, *h512, *wh;
    __nv_bfloat16 *hm_bf, *y_bf, *wbf;
    float *part, *z, *w;
    cudaGetSymbolAddress((void**)&h384,  g_h384);
    cudaGetSymbolAddress((void**)&h512,  g_h512);
    cudaGetSymbolAddress((void**)&part,  g_part);
    cudaGetSymbolAddress((void**)&hm_bf, g_hm_bf);
    cudaGetSymbolAddress((void**)&y_bf,  g_y_bf);
    cudaGetSymbolAddress((void**)&z,     g_z);
    cudaGetSymbolAddress((void**)&w,     g_w);
    cudaGetSymbolAddress((void**)&wh,    g_wh);
    cudaGetSymbolAddress((void**)&wbf,   g_wbf);

    __half* awt = wh;
    __half* bwt = awt + AWT_SZ;
    __half* p1t = bwt + BWT_SZ;
    __half* p2t = p1t + P1T_SZ;
    __nv_bfloat16* p3t = wbf;
    __nv_bfloat16* f1t = wbf + P3T_SZ;

    prep_all<<<(PREP_TOTAL + 255) / 256, 256>>>(aw, bw, p1w, p2w, p3w, f1w, wh, wbf, part);

    const int NT = (P + 127) / 128;

    embed_all<<<NT, 256, SMEM_EA>>>(pairs, awt, bwt, ab, bb, h384, P);
    tc_gemm_h<<<dim3(NT, 4), 256, SMEM_V2>>>(h384, 384, p1t, p1b, h512, 512, P, 384);
    fused_p2_segsum<<<NT, 256, SMEM_P2>>>(h512, p2t, p2b, part, P, group, B);
    hm_combine<<<(B * 256 + 255) / 256, 256>>>(part, idx_pairs, hm_bf, B);

    const int BT = (B + 127) / 128;
    tc_gemm_v2<<<dim3(BT, 8), 256, SMEM_V2>>>(hm_bf, 256, p3t, p3b, y_bf, 1024, B, 256, 0, 1);
    tc_gemm_v2<<<dim3(BT, 4), 256, SMEM_V2>>>(y_bf, 1024, f1t, f1b, z, 512, B, 1024, 1, 0);
    gemm_simt<<<(B + 63) / 64, 256>>>(z, 512, f2w, 32, f2b, w, 32, B, 32, 512, 1);
    final_kernel<<<(B + 255) / 256, 256>>>(w, f3w, f3b, out, B);
}

// round 15
// speedup vs baseline: 1.0347x; 1.0347x over previous
#include <cuda_runtime.h>
#include <cuda_bf16.h>
#include <cstdint>

// ===========================================================================
// TGNN R15 — R9 champion configuration restored verbatim + f2/final fusion.
//   prep_all       : all weight transforms + partial zeroing, ONE launch
//   embed_all      : fp32 pairs -> (in-reg bf16) -> 3 embed GEMMs -> h384
//   tc_gemm_v2     : generic bf16 GEMM, BK=64, 1 barrier per 64k (p1, p3, f1)
//   fused_p2_segsum: p2 BK=64 + deterministic segment sums
//   f2_final       : fused z->w->out SIMT fp32
// ===========================================================================

#define P_MAX  200000
#define B_MAX  2000

__device__ __nv_bfloat16 g_h384[(size_t)P_MAX * 384];
__device__ __nv_bfloat16 g_h512[(size_t)P_MAX * 512];
__device__ float g_part[2 * (size_t)B_MAX * 256];
__device__ __nv_bfloat16 g_hm_bf[(size_t)B_MAX * 256];
__device__ __nv_bfloat16 g_y_bf [(size_t)B_MAX * 1024];
__device__ float g_z   [(size_t)B_MAX * 512];
__device__ __nv_bfloat16 g_wbf[2 * 1024 * 1024];

// ---------------------------------------------------------------------------
__device__ __forceinline__ uint32_t bf2_bits(float lo, float hi) {
    __nv_bfloat162 p = __float22bfloat162_rn(make_float2(lo, hi));
    return *reinterpret_cast<uint32_t*>(&p);
}
__device__ __forceinline__ void cp_async16(uint32_t smem_addr, const void* gptr, int src_bytes) {
    asm volatile("cp.async.ca.shared.global [%0], [%1], 16, %2;\n"
                 :: "r"(smem_addr), "l"(gptr), "r"(src_bytes));
}
#define CP_ASYNC_COMMIT() asm volatile("cp.async.commit_group;\n" ::: "memory")
#define CP_ASYNC_WAIT0()  asm volatile("cp.async.wait_group 0;\n" ::: "memory")

__device__ __forceinline__ uint32_t smem_u32(const void* p) {
    uint32_t a;
    asm("{ .reg .u64 t; cvta.to.shared.u64 t, %1; cvt.u32.u64 %0, t; }" : "=r"(a) : "l"(p));
    return a;
}
__device__ __forceinline__ void mma_bf16(float& c0, float& c1, float& c2, float& c3,
                                         uint32_t a0, uint32_t a1, uint32_t a2, uint32_t a3,
                                         uint32_t b0, uint32_t b1) {
    asm volatile(
        "mma.sync.aligned.m16n8k16.row.col.f32.bf16.bf16.f32 "
        "{%0,%1,%2,%3}, {%4,%5,%6,%7}, {%8,%9}, {%0,%1,%2,%3};"
        : "+f"(c0), "+f"(c1), "+f"(c2), "+f"(c3)
        : "r"(a0), "r"(a1), "r"(a2), "r"(a3), "r"(b0), "r"(b1));
}
__device__ __forceinline__ void ldsm_x4(uint32_t* r, uint32_t addr) {
    asm volatile("ldmatrix.sync.aligned.m8n8.x4.shared.b16 {%0,%1,%2,%3}, [%4];"
                 : "=r"(r[0]), "=r"(r[1]), "=r"(r[2]), "=r"(r[3]) : "r"(addr));
}

// ---------------------------------------------------------------------------
// Tile block = 128 rows x 32 k bf16; smem row = 64B data + 16B pad (80B).
// ---------------------------------------------------------------------------
#define TILE_B 10240

__device__ __forceinline__ void load_tile(uint32_t dst, const __nv_bfloat16* __restrict__ src,
                                          int ld, int rbase, int rmax, int k0, int tid)
{
#pragma unroll
    for (int h = 0; h < 2; h++) {
        const int chunk = tid + h * 256;
        const int row = chunk >> 2;
        const int ck  = chunk & 3;
        const int gr  = rbase + row;
        const char* p = (const char*)(src + (size_t)gr * ld + k0 + ck * 8);
        cp_async16(dst + row * 80 + ck * 16, p, gr < rmax ? 16 : 0);
    }
}

// ldmatrix k32 block (proven R8 mapping)
__device__ __forceinline__ void mma_block_ldsm(uint32_t Abase, uint32_t Bbase,
                                               float acc[2][8][4],
                                               int lane, int warp_m, int warp_n)
{
    const int l7  = lane & 7;
    const int lb3 = (lane >> 3) & 1;
    const int lb4 = lane >> 4;
#pragma unroll
    for (int ks = 0; ks < 2; ks++) {
        uint32_t a[2][4];
#pragma unroll
        for (int mt = 0; mt < 2; mt++) {
            uint32_t addr = Abase + (uint32_t)(warp_m + mt * 16 + lb3 * 8 + l7) * 80
                          + ks * 32 + lb4 * 16;
            ldsm_x4(a[mt], addr);
        }
        uint32_t b[8][2];
#pragma unroll
        for (int np = 0; np < 4; np++) {
            uint32_t r[4];
            uint32_t addr = Bbase + (uint32_t)(warp_n + np * 16 + lb4 * 8 + l7) * 80
                          + ks * 32 + lb3 * 16;
            ldsm_x4(r, addr);
            b[2 * np][0]     = r[0];
            b[2 * np][1]     = r[1];
            b[2 * np + 1][0] = r[2];
            b[2 * np + 1][1] = r[3];
        }
#pragma unroll
        for (int mt = 0; mt < 2; mt++)
#pragma unroll
            for (int nt = 0; nt < 8; nt++)
                mma_bf16(acc[mt][nt][0], acc[mt][nt][1], acc[mt][nt][2], acc[mt][nt][3],
                         a[mt][0], a[mt][1], a[mt][2], a[mt][3],
                         b[nt][0], b[nt][1]);
    }
}

// ===========================================================================
// embed_all (proven R8): one CTA = 128 rows, three embed slabs. 81920 B smem.
// ===========================================================================
#define SMEM_EA (5 * TILE_B + 3 * TILE_B)

__global__ __launch_bounds__(256)
void embed_all(const float* __restrict__ pairs,
               const __nv_bfloat16* __restrict__ awt,
               const __nv_bfloat16* __restrict__ bwt,
               const float* __restrict__ ab, const float* __restrict__ bb,
               __nv_bfloat16* __restrict__ h384, int P)
{
    extern __shared__ char smem[];
    const uint32_t smem_base = smem_u32(smem);

    const int tid = threadIdx.x;
    const int wid = tid >> 5, lane = tid & 31;
    const int g = lane >> 2, t = lane & 3;
    const int warp_m = (wid & 3) * 32;
    const int warp_n = (wid >> 2) * 64;
    const int blockRow = blockIdx.x * 128;

    load_tile(smem_base + 5 * TILE_B,          awt, 64, 0, 1 << 30, 0,  tid);
    load_tile(smem_base + 5 * TILE_B + TILE_B, awt, 64, 0, 1 << 30, 32, tid);
    load_tile(smem_base + 7 * TILE_B,          bwt, 32, 0, 1 << 30, 0,  tid);
    CP_ASYNC_COMMIT();

    {
        const int r = tid >> 1;
        const int h = tid & 1;
        const int gr = blockRow + r;
        const bool ok = (gr < P);
        const float* rp = pairs + (size_t)gr * 160 + h * 80;
#pragma unroll
        for (int i = 0; i < 20; i++) {
            float4 v = ok ? *reinterpret_cast<const float4*>(rp + i * 4)
                          : make_float4(0.f, 0.f, 0.f, 0.f);
            const int col = h * 80 + i * 4;
            const int kb = col >> 5, kin = col & 31;
            uint2 pk;
            pk.x = bf2_bits(v.x, v.y);
            pk.y = bf2_bits(v.z, v.w);
            *reinterpret_cast<uint2*>(smem + kb * TILE_B + r * 80 + kin * 2) = pk;
        }
    }
    CP_ASYNC_WAIT0();
    __syncthreads();

    float acc[2][8][4];
#pragma unroll
    for (int c = 0; c < 3; c++) {
        const int nkb = (c < 2) ? 2 : 1;
        const int ab0 = c * 2;
        const uint32_t woff = (c < 2) ? 5 * TILE_B : 7 * TILE_B;
        const float* biasc = (c < 2) ? ab : bb;

#pragma unroll
        for (int mt = 0; mt < 2; mt++)
#pragma unroll
            for (int nt = 0; nt < 8; nt++)
#pragma unroll
                for (int i = 0; i < 4; i++) acc[mt][nt][i] = 0.0f;

        for (int kb = 0; kb < nkb; kb++)
            mma_block_ldsm(smem_base + (ab0 + kb) * TILE_B,
                           smem_base + woff + kb * TILE_B,
                           acc, lane, warp_m, warp_n);

#pragma unroll
        for (int nt = 0; nt < 8; nt++) {
            const int col = warp_n + nt * 8 + 2 * t;
            const float2 bv = *(const float2*)&biasc[col];
#pragma unroll
            for (int mt = 0; mt < 2; mt++)
#pragma unroll
                for (int half = 0; half < 2; half++) {
                    const int row = blockRow + warp_m + mt * 16 + half * 8 + g;
                    if (row >= P) continue;
                    float v0 = fmaxf(acc[mt][nt][half * 2 + 0] + bv.x, 0.f);
                    float v1 = fmaxf(acc[mt][nt][half * 2 + 1] + bv.y, 0.f);
                    *(__nv_bfloat162*)(h384 + (size_t)row * 384 + c * 128 + col) =
                        __float22bfloat162_rn(make_float2(v0, v1));
                }
        }
    }
}

// ===========================================================================
// tc_gemm_v2 (proven R9): BK=64, 2-stage double buffer, 1 barrier per 64k.
// ===========================================================================
#define STAGE64  (4 * TILE_B)
#define SMEM_V2  (2 * STAGE64)

__global__ __launch_bounds__(256)
void tc_gemm_v2(const __nv_bfloat16* __restrict__ A, int lda,
                const __nv_bfloat16* __restrict__ WT,
                const float* __restrict__ bias,
                void* __restrict__ Cv, int ldc,
                int M, int K, int relu, int out_bf16)
{
    extern __shared__ char smem[];
    const uint32_t smem_base = smem_u32(smem);

    const int tid  = threadIdx.x;
    const int wid  = tid >> 5, lane = tid & 31;
    const int g    = lane >> 2, t = lane & 3;

    const int blockRow = blockIdx.x * 128;
    const int blockCol = blockIdx.y * 128;
    const int warp_m = (wid & 3) * 32;
    const int warp_n = (wid >> 2) * 64;

    const int NIT = K >> 6;

    float acc[2][8][4];
#pragma unroll
    for (int mt = 0; mt < 2; mt++)
#pragma unroll
        for (int nt = 0; nt < 8; nt++)
#pragma unroll
            for (int i = 0; i < 4; i++) acc[mt][nt][i] = 0.0f;

    auto load_stage = [&](int it) {
        const uint32_t base = smem_base + (it & 1) * STAGE64;
        const int k0 = it * 64;
        load_tile(base,              A,  lda, blockRow, M,       k0,      tid);
        load_tile(base + TILE_B,     A,  lda, blockRow, M,       k0 + 32, tid);
        load_tile(base + 2 * TILE_B, WT, K,   blockCol, 1 << 30, k0,      tid);
        load_tile(base + 3 * TILE_B, WT, K,   blockCol, 1 << 30, k0 + 32, tid);
        CP_ASYNC_COMMIT();
    };

    load_stage(0);

    for (int it = 0; it < NIT; it++) {
        CP_ASYNC_WAIT0();
        __syncthreads();
        if (it + 1 < NIT) load_stage(it + 1);
        const uint32_t base = smem_base + (it & 1) * STAGE64;
        mma_block_ldsm(base,          base + 2 * TILE_B, acc, lane, warp_m, warp_n);
        mma_block_ldsm(base + TILE_B, base + 3 * TILE_B, acc, lane, warp_m, warp_n);
    }

#pragma unroll
    for (int nt = 0; nt < 8; nt++) {
        const int col = blockCol + warp_n + nt * 8 + 2 * t;
        const float2 bv = *reinterpret_cast<const float2*>(&bias[col]);
#pragma unroll
        for (int mt = 0; mt < 2; mt++)
#pragma unroll
            for (int half = 0; half < 2; half++) {
                const int row = blockRow + warp_m + mt * 16 + half * 8 + g;
                if (row >= M) continue;
                float v0 = acc[mt][nt][half * 2 + 0] + bv.x;
                float v1 = acc[mt][nt][half * 2 + 1] + bv.y;
                if (relu) { v0 = fmaxf(v0, 0.f); v1 = fmaxf(v1, 0.f); }
                if (out_bf16) {
                    *(__nv_bfloat162*)((__nv_bfloat16*)Cv + (size_t)row * ldc + col) =
                        __float22bfloat162_rn(make_float2(v0, v1));
                } else {
                    *reinterpret_cast<float2*>((float*)Cv + (size_t)row * ldc + col) =
                        make_float2(v0, v1);
                }
            }
    }
}

// ===========================================================================
// fused_p2_segsum (proven R9): p2 BK=64 + deterministic segment sums.
// ===========================================================================
#define REDPAD 129
#define SMEM_P2 (2 * STAGE64)   // 81920 >= 128*129*4

__global__ __launch_bounds__(256)
void fused_p2_segsum(const __nv_bfloat16* __restrict__ h512,
                     const __nv_bfloat16* __restrict__ p2t,
                     const float* __restrict__ p2b,
                     float* __restrict__ part, int P, int group, int Bseg)
{
    extern __shared__ char smem[];
    const uint32_t smem_base = smem_u32(smem);
    float* red = (float*)smem;

    const int tid = threadIdx.x;
    const int wid = tid >> 5, lane = tid & 31;
    const int g = lane >> 2, t = lane & 3;
    const int warp_m = (wid & 3) * 32;
    const int warp_n = (wid >> 2) * 64;
    const int blockRow = blockIdx.x * 128;

    float acc[2][8][4];

    for (int nc = 0; nc < 2; nc++) {
#pragma unroll
        for (int mt = 0; mt < 2; mt++)
#pragma unroll
            for (int nt = 0; nt < 8; nt++)
#pragma unroll
                for (int i = 0; i < 4; i++) acc[mt][nt][i] = 0.0f;

        auto load_stage = [&](int it) {
            const uint32_t base = smem_base + (it & 1) * STAGE64;
            const int k0 = it * 64;
            load_tile(base,              h512, 512, blockRow, P,       k0,      tid);
            load_tile(base + TILE_B,     h512, 512, blockRow, P,       k0 + 32, tid);
            load_tile(base + 2 * TILE_B, p2t,  512, nc * 128, 1 << 30, k0,      tid);
            load_tile(base + 3 * TILE_B, p2t,  512, nc * 128, 1 << 30, k0 + 32, tid);
            CP_ASYNC_COMMIT();
        };

        load_stage(0);
        for (int it = 0; it < 8; it++) {          // K=512 -> 8 blocks of 64
            CP_ASYNC_WAIT0();
            __syncthreads();
            if (it + 1 < 8) load_stage(it + 1);
            const uint32_t base = smem_base + (it & 1) * STAGE64;
            mma_block_ldsm(base,          base + 2 * TILE_B, acc, lane, warp_m, warp_n);
            mma_block_ldsm(base + TILE_B, base + 3 * TILE_B, acc, lane, warp_m, warp_n);
        }
        __syncthreads();   // drain before red aliases the stages

#pragma unroll
        for (int nt = 0; nt < 8; nt++) {
            const int col = warp_n + nt * 8 + 2 * t;
            const float2 bv = *(const float2*)&p2b[nc * 128 + col];
#pragma unroll
            for (int mt = 0; mt < 2; mt++)
#pragma unroll
                for (int half = 0; half < 2; half++) {
                    const int row = warp_m + mt * 16 + half * 8 + g;
                    red[row * REDPAD + col]     = fmaxf(acc[mt][nt][half * 2 + 0] + bv.x, 0.f);
                    red[row * REDPAD + col + 1] = fmaxf(acc[mt][nt][half * 2 + 1] + bv.y, 0.f);
                }
        }
        __syncthreads();

        {
            const int col = tid & 127;
            const int rb  = (tid >> 7) * 64;
            float s = 0.f;
            bool any = false;
            int curseg = 0, nxt = 0;
            for (int r = rb; r < rb + 64; r++) {
                const int grow = blockRow + r;
                if (grow >= P) break;
                if (!any) {
                    curseg = grow / group;
                    nxt = (curseg + 1) * group;
                    any = true;
                } else if (grow >= nxt) {
                    const int slot = blockIdx.x - (curseg * group) / 128;
                    atomicAdd(&part[(size_t)slot * Bseg * 256 + curseg * 256 + nc * 128 + col], s);
                    s = 0.f;
                    curseg++;
                    nxt += group;
                }
                s += red[r * REDPAD + col];
            }
            if (any) {
                const int slot = blockIdx.x - (curseg * group) / 128;
                atomicAdd(&part[(size_t)slot * Bseg * 256 + curseg * 256 + nc * 128 + col], s);
            }
        }
        __syncthreads();
    }
}

// ===========================================================================
// prep_all (proven R9)
// ===========================================================================
#define AWT_SZ  (128 * 64)
#define BWT_SZ  (128 * 32)
#define P1T_SZ  (512 * 384)
#define P2T_SZ  (256 * 512)
#define P3T_SZ  (1024 * 256)
#define F1T_SZ  (512 * 1024)
#define ZERO_SZ (2 * B_MAX * 256)
#define PREP_TOTAL (AWT_SZ + BWT_SZ + P1T_SZ + P2T_SZ + P3T_SZ + F1T_SZ + ZERO_SZ)

__global__ void prep_all(const float* __restrict__ aw,  const float* __restrict__ bw,
                         const float* __restrict__ p1w, const float* __restrict__ p2w,
                         const float* __restrict__ p3w, const float* __restrict__ f1w,
                         __nv_bfloat16* __restrict__ wbf, float* __restrict__ part)
{
    int i = blockIdx.x * blockDim.x + threadIdx.x;
    if (i >= PREP_TOTAL) return;
    int off = 0;
    if (i < off + AWT_SZ) {
        int j = i - off; int n = j / 64, k = j % 64;
        wbf[i] = __float2bfloat16(aw[(size_t)k * 128 + n]); return;
    } off += AWT_SZ;
    if (i < off + BWT_SZ) {
        int j = i - off; int n = j / 32, k = j % 32;
        wbf[i] = __float2bfloat16(bw[(size_t)k * 128 + n]); return;
    } off += BWT_SZ;
    if (i < off + P1T_SZ) {
        int j = i - off; int n = j / 384, k = j % 384;
        wbf[i] = __float2bfloat16(p1w[(size_t)k * 512 + n]); return;
    } off += P1T_SZ;
    if (i < off + P2T_SZ) {
        int j = i - off; int n = j / 512, k = j % 512;
        wbf[i] = __float2bfloat16(p2w[(size_t)k * 256 + n]); return;
    } off += P2T_SZ;
    if (i < off + P3T_SZ) {
        int j = i - off; int n = j / 256, k = j % 256;
        wbf[i] = __float2bfloat16(p3w[(size_t)k * 1024 + n]); return;
    } off += P3T_SZ;
    if (i < off + F1T_SZ) {
        int j = i - off; int n = j / 1024, k = j % 1024;
        wbf[i] = __float2bfloat16(f1w[(size_t)k * 512 + n]); return;
    } off += F1T_SZ;
    part[i - off] = 0.0f;
}

// ---------------------------------------------------------------------------
__global__ void hm_combine(const float* __restrict__ part, const int* __restrict__ idx,
                           __nv_bfloat16* __restrict__ hm, int Bseg)
{
    int i = blockIdx.x * blockDim.x + threadIdx.x;
    if (i >= Bseg * 256) return;
    int s = i >> 8;
    hm[i] = __float2bfloat16((part[i] + part[(size_t)Bseg * 256 + i]) / (float)idx[s]);
}

// ---------------------------------------------------------------------------
// f2_final: fused  w = relu(z @ f2w + f2b);  out = w @ f3w + f3b
//   64 rows per block; 4 threads per row compute 8 cols each, then the
//   row-leader reduces the 32-wide dot via shuffle-free smem (exact fp32
//   same-order sum as the separate kernels: k ascending).
// ---------------------------------------------------------------------------
__global__ __launch_bounds__(256, 2)
void f2_final(const float* __restrict__ z,
              const float* __restrict__ f2w, const float* __restrict__ f2b,
              const float* __restrict__ f3w, const float* __restrict__ f3b,
              float* __restrict__ out, int B)
{
    __shared__ float wsh[64][33];
    const int rloc = threadIdx.x >> 2;           // 0..63
    const int nq   = (threadIdx.x & 3) * 8;
    const int gm   = blockIdx.x * 64 + rloc;

    if (gm < B) {
        float acc[8] = {0,0,0,0,0,0,0,0};
        const float* a = z + (size_t)gm * 512;
        for (int k = 0; k < 512; k++) {
            float av = a[k];
            const float* wr = f2w + (size_t)k * 32 + nq;
#pragma unroll
            for (int j = 0; j < 8; j++) acc[j] = fmaf(av, wr[j], acc[j]);
        }
#pragma unroll
        for (int j = 0; j < 8; j++)
            wsh[rloc][nq + j] = fmaxf(acc[j] + f2b[nq + j], 0.0f);
    }
    __syncthreads();

    if ((threadIdx.x & 3) == 0 && gm < B) {
        float s = 0.0f;
#pragma unroll
        for (int k = 0; k < 32; k++) s = fmaf(wsh[rloc][k], f3w[k], s);
        out[gm] = s + f3b[0];
    }
}

// ---------------------------------------------------------------------------
extern "C" void kernel_launch(void* const* d_in, const int* in_sizes, int n_in,
                              void* d_out, int out_size)
{
    const float* pairs     = (const float*)d_in[0];
    const int*   idx_pairs = (const int*)  d_in[1];
    const float* aw  = (const float*)d_in[3];
    const float* ab  = (const float*)d_in[4];
    const float* bw  = (const float*)d_in[5];
    const float* bb  = (const float*)d_in[6];
    const float* p1w = (const float*)d_in[7];
    const float* p1b = (const float*)d_in[8];
    const float* p2w = (const float*)d_in[9];
    const float* p2b = (const float*)d_in[10];
    const float* p3w = (const float*)d_in[11];
    const float* p3b = (const float*)d_in[12];
    const float* f1w = (const float*)d_in[13];
    const float* f1b = (const float*)d_in[14];
    const float* f2w = (const float*)d_in[15];
    const float* f2b = (const float*)d_in[16];
    const float* f3w = (const float*)d_in[17];
    const float* f3b = (const float*)d_in[18];
    float* out = (float*)d_out;

    const int P = in_sizes[0] / 160;
    const int B = in_sizes[1];
    const int group = P / B;

    cudaFuncSetAttribute(embed_all,       cudaFuncAttributeMaxDynamicSharedMemorySize, SMEM_EA);
    cudaFuncSetAttribute(tc_gemm_v2,      cudaFuncAttributeMaxDynamicSharedMemorySize, SMEM_V2);
    cudaFuncSetAttribute(fused_p2_segsum, cudaFuncAttributeMaxDynamicSharedMemorySize, SMEM_P2);

    __nv_bfloat16 *h384, *h512, *hm_bf, *y_bf, *wbf;
    float *part, *z;
    cudaGetSymbolAddress((void**)&h384,  g_h384);
    cudaGetSymbolAddress((void**)&h512,  g_h512);
    cudaGetSymbolAddress((void**)&part,  g_part);
    cudaGetSymbolAddress((void**)&hm_bf, g_hm_bf);
    cudaGetSymbolAddress((void**)&y_bf,  g_y_bf);
    cudaGetSymbolAddress((void**)&z,     g_z);
    cudaGetSymbolAddress((void**)&wbf,   g_wbf);

    __nv_bfloat16* awt = wbf;
    __nv_bfloat16* bwt = awt + AWT_SZ;
    __nv_bfloat16* p1t = bwt + BWT_SZ;
    __nv_bfloat16* p2t = p1t + P1T_SZ;
    __nv_bfloat16* p3t = p2t + P2T_SZ;
    __nv_bfloat16* f1t = p3t + P3T_SZ;

    prep_all<<<(PREP_TOTAL + 255) / 256, 256>>>(aw, bw, p1w, p2w, p3w, f1w, wbf, part);

    const int NT = (P + 127) / 128;

    embed_all<<<NT, 256, SMEM_EA>>>(pairs, awt, bwt, ab, bb, h384, P);
    tc_gemm_v2<<<dim3(NT, 4), 256, SMEM_V2>>>(h384, 384, p1t, p1b, h512, 512, P, 384, 1, 1);
    fused_p2_segsum<<<NT, 256, SMEM_P2>>>(h512, p2t, p2b, part, P, group, B);
    hm_combine<<<(B * 256 + 255) / 256, 256>>>(part, idx_pairs, hm_bf, B);

    const int BT = (B + 127) / 128;
    tc_gemm_v2<<<dim3(BT, 8), 256, SMEM_V2>>>(hm_bf, 256, p3t, p3b, y_bf, 1024, B, 256, 0, 1);
    tc_gemm_v2<<<dim3(BT, 4), 256, SMEM_V2>>>(y_bf, 1024, f1t, f1b, z, 512, B, 1024, 1, 0);
    f2_final<<<(B + 63) / 64, 256>>>(z, f2w, f2b, f3w, f3b, out, B);
}

// round 16
// speedup vs baseline: 1.0692x; 1.0333x over previous
#include <cuda_runtime.h>
#include <cuda_bf16.h>
#include <cstdint>

// ===========================================================================
// TGNN R16 — champion (R15, 696.3us) + vectorized f2_final.
//   prep_all       : all weight transforms + partial zeroing, ONE launch
//   embed_all      : fp32 pairs -> (in-reg bf16) -> 3 embed GEMMs -> h384
//   tc_gemm_v2     : generic bf16 GEMM, BK=64, 1 barrier per 64k (p1, p3, f1)
//   fused_p2_segsum: p2 BK=64 + deterministic segment sums
//   f2_final       : fused z->w->out SIMT fp32 (float4 loads)
// ===========================================================================

#define P_MAX  200000
#define B_MAX  2000

__device__ __nv_bfloat16 g_h384[(size_t)P_MAX * 384];
__device__ __nv_bfloat16 g_h512[(size_t)P_MAX * 512];
__device__ float g_part[2 * (size_t)B_MAX * 256];
__device__ __nv_bfloat16 g_hm_bf[(size_t)B_MAX * 256];
__device__ __nv_bfloat16 g_y_bf [(size_t)B_MAX * 1024];
__device__ float g_z   [(size_t)B_MAX * 512];
__device__ __nv_bfloat16 g_wbf[2 * 1024 * 1024];

// ---------------------------------------------------------------------------
__device__ __forceinline__ uint32_t bf2_bits(float lo, float hi) {
    __nv_bfloat162 p = __float22bfloat162_rn(make_float2(lo, hi));
    return *reinterpret_cast<uint32_t*>(&p);
}
__device__ __forceinline__ void cp_async16(uint32_t smem_addr, const void* gptr, int src_bytes) {
    asm volatile("cp.async.ca.shared.global [%0], [%1], 16, %2;\n"
                 :: "r"(smem_addr), "l"(gptr), "r"(src_bytes));
}
#define CP_ASYNC_COMMIT() asm volatile("cp.async.commit_group;\n" ::: "memory")
#define CP_ASYNC_WAIT0()  asm volatile("cp.async.wait_group 0;\n" ::: "memory")

__device__ __forceinline__ uint32_t smem_u32(const void* p) {
    uint32_t a;
    asm("{ .reg .u64 t; cvta.to.shared.u64 t, %1; cvt.u32.u64 %0, t; }" : "=r"(a) : "l"(p));
    return a;
}
__device__ __forceinline__ void mma_bf16(float& c0, float& c1, float& c2, float& c3,
                                         uint32_t a0, uint32_t a1, uint32_t a2, uint32_t a3,
                                         uint32_t b0, uint32_t b1) {
    asm volatile(
        "mma.sync.aligned.m16n8k16.row.col.f32.bf16.bf16.f32 "
        "{%0,%1,%2,%3}, {%4,%5,%6,%7}, {%8,%9}, {%0,%1,%2,%3};"
        : "+f"(c0), "+f"(c1), "+f"(c2), "+f"(c3)
        : "r"(a0), "r"(a1), "r"(a2), "r"(a3), "r"(b0), "r"(b1));
}
__device__ __forceinline__ void ldsm_x4(uint32_t* r, uint32_t addr) {
    asm volatile("ldmatrix.sync.aligned.m8n8.x4.shared.b16 {%0,%1,%2,%3}, [%4];"
                 : "=r"(r[0]), "=r"(r[1]), "=r"(r[2]), "=r"(r[3]) : "r"(addr));
}

// ---------------------------------------------------------------------------
// Tile block = 128 rows x 32 k bf16; smem row = 64B data + 16B pad (80B).
// ---------------------------------------------------------------------------
#define TILE_B 10240

__device__ __forceinline__ void load_tile(uint32_t dst, const __nv_bfloat16* __restrict__ src,
                                          int ld, int rbase, int rmax, int k0, int tid)
{
#pragma unroll
    for (int h = 0; h < 2; h++) {
        const int chunk = tid + h * 256;
        const int row = chunk >> 2;
        const int ck  = chunk & 3;
        const int gr  = rbase + row;
        const char* p = (const char*)(src + (size_t)gr * ld + k0 + ck * 8);
        cp_async16(dst + row * 80 + ck * 16, p, gr < rmax ? 16 : 0);
    }
}

// ldmatrix k32 block (proven R8 mapping)
__device__ __forceinline__ void mma_block_ldsm(uint32_t Abase, uint32_t Bbase,
                                               float acc[2][8][4],
                                               int lane, int warp_m, int warp_n)
{
    const int l7  = lane & 7;
    const int lb3 = (lane >> 3) & 1;
    const int lb4 = lane >> 4;
#pragma unroll
    for (int ks = 0; ks < 2; ks++) {
        uint32_t a[2][4];
#pragma unroll
        for (int mt = 0; mt < 2; mt++) {
            uint32_t addr = Abase + (uint32_t)(warp_m + mt * 16 + lb3 * 8 + l7) * 80
                          + ks * 32 + lb4 * 16;
            ldsm_x4(a[mt], addr);
        }
        uint32_t b[8][2];
#pragma unroll
        for (int np = 0; np < 4; np++) {
            uint32_t r[4];
            uint32_t addr = Bbase + (uint32_t)(warp_n + np * 16 + lb4 * 8 + l7) * 80
                          + ks * 32 + lb3 * 16;
            ldsm_x4(r, addr);
            b[2 * np][0]     = r[0];
            b[2 * np][1]     = r[1];
            b[2 * np + 1][0] = r[2];
            b[2 * np + 1][1] = r[3];
        }
#pragma unroll
        for (int mt = 0; mt < 2; mt++)
#pragma unroll
            for (int nt = 0; nt < 8; nt++)
                mma_bf16(acc[mt][nt][0], acc[mt][nt][1], acc[mt][nt][2], acc[mt][nt][3],
                         a[mt][0], a[mt][1], a[mt][2], a[mt][3],
                         b[nt][0], b[nt][1]);
    }
}

// ===========================================================================
// embed_all (proven R8): one CTA = 128 rows, three embed slabs. 81920 B smem.
// ===========================================================================
#define SMEM_EA (5 * TILE_B + 3 * TILE_B)

__global__ __launch_bounds__(256)
void embed_all(const float* __restrict__ pairs,
               const __nv_bfloat16* __restrict__ awt,
               const __nv_bfloat16* __restrict__ bwt,
               const float* __restrict__ ab, const float* __restrict__ bb,
               __nv_bfloat16* __restrict__ h384, int P)
{
    extern __shared__ char smem[];
    const uint32_t smem_base = smem_u32(smem);

    const int tid = threadIdx.x;
    const int wid = tid >> 5, lane = tid & 31;
    const int g = lane >> 2, t = lane & 3;
    const int warp_m = (wid & 3) * 32;
    const int warp_n = (wid >> 2) * 64;
    const int blockRow = blockIdx.x * 128;

    load_tile(smem_base + 5 * TILE_B,          awt, 64, 0, 1 << 30, 0,  tid);
    load_tile(smem_base + 5 * TILE_B + TILE_B, awt, 64, 0, 1 << 30, 32, tid);
    load_tile(smem_base + 7 * TILE_B,          bwt, 32, 0, 1 << 30, 0,  tid);
    CP_ASYNC_COMMIT();

    {
        const int r = tid >> 1;
        const int h = tid & 1;
        const int gr = blockRow + r;
        const bool ok = (gr < P);
        const float* rp = pairs + (size_t)gr * 160 + h * 80;
#pragma unroll
        for (int i = 0; i < 20; i++) {
            float4 v = ok ? *reinterpret_cast<const float4*>(rp + i * 4)
                          : make_float4(0.f, 0.f, 0.f, 0.f);
            const int col = h * 80 + i * 4;
            const int kb = col >> 5, kin = col & 31;
            uint2 pk;
            pk.x = bf2_bits(v.x, v.y);
            pk.y = bf2_bits(v.z, v.w);
            *reinterpret_cast<uint2*>(smem + kb * TILE_B + r * 80 + kin * 2) = pk;
        }
    }
    CP_ASYNC_WAIT0();
    __syncthreads();

    float acc[2][8][4];
#pragma unroll
    for (int c = 0; c < 3; c++) {
        const int nkb = (c < 2) ? 2 : 1;
        const int ab0 = c * 2;
        const uint32_t woff = (c < 2) ? 5 * TILE_B : 7 * TILE_B;
        const float* biasc = (c < 2) ? ab : bb;

#pragma unroll
        for (int mt = 0; mt < 2; mt++)
#pragma unroll
            for (int nt = 0; nt < 8; nt++)
#pragma unroll
                for (int i = 0; i < 4; i++) acc[mt][nt][i] = 0.0f;

        for (int kb = 0; kb < nkb; kb++)
            mma_block_ldsm(smem_base + (ab0 + kb) * TILE_B,
                           smem_base + woff + kb * TILE_B,
                           acc, lane, warp_m, warp_n);

#pragma unroll
        for (int nt = 0; nt < 8; nt++) {
            const int col = warp_n + nt * 8 + 2 * t;
            const float2 bv = *(const float2*)&biasc[col];
#pragma unroll
            for (int mt = 0; mt < 2; mt++)
#pragma unroll
                for (int half = 0; half < 2; half++) {
                    const int row = blockRow + warp_m + mt * 16 + half * 8 + g;
                    if (row >= P) continue;
                    float v0 = fmaxf(acc[mt][nt][half * 2 + 0] + bv.x, 0.f);
                    float v1 = fmaxf(acc[mt][nt][half * 2 + 1] + bv.y, 0.f);
                    *(__nv_bfloat162*)(h384 + (size_t)row * 384 + c * 128 + col) =
                        __float22bfloat162_rn(make_float2(v0, v1));
                }
        }
    }
}

// ===========================================================================
// tc_gemm_v2 (proven R9): BK=64, 2-stage double buffer, 1 barrier per 64k.
// ===========================================================================
#define STAGE64  (4 * TILE_B)
#define SMEM_V2  (2 * STAGE64)

__global__ __launch_bounds__(256)
void tc_gemm_v2(const __nv_bfloat16* __restrict__ A, int lda,
                const __nv_bfloat16* __restrict__ WT,
                const float* __restrict__ bias,
                void* __restrict__ Cv, int ldc,
                int M, int K, int relu, int out_bf16)
{
    extern __shared__ char smem[];
    const uint32_t smem_base = smem_u32(smem);

    const int tid  = threadIdx.x;
    const int wid  = tid >> 5, lane = tid & 31;
    const int g    = lane >> 2, t = lane & 3;

    const int blockRow = blockIdx.x * 128;
    const int blockCol = blockIdx.y * 128;
    const int warp_m = (wid & 3) * 32;
    const int warp_n = (wid >> 2) * 64;

    const int NIT = K >> 6;

    float acc[2][8][4];
#pragma unroll
    for (int mt = 0; mt < 2; mt++)
#pragma unroll
        for (int nt = 0; nt < 8; nt++)
#pragma unroll
            for (int i = 0; i < 4; i++) acc[mt][nt][i] = 0.0f;

    auto load_stage = [&](int it) {
        const uint32_t base = smem_base + (it & 1) * STAGE64;
        const int k0 = it * 64;
        load_tile(base,              A,  lda, blockRow, M,       k0,      tid);
        load_tile(base + TILE_B,     A,  lda, blockRow, M,       k0 + 32, tid);
        load_tile(base + 2 * TILE_B, WT, K,   blockCol, 1 << 30, k0,      tid);
        load_tile(base + 3 * TILE_B, WT, K,   blockCol, 1 << 30, k0 + 32, tid);
        CP_ASYNC_COMMIT();
    };

    load_stage(0);

    for (int it = 0; it < NIT; it++) {
        CP_ASYNC_WAIT0();
        __syncthreads();
        if (it + 1 < NIT) load_stage(it + 1);
        const uint32_t base = smem_base + (it & 1) * STAGE64;
        mma_block_ldsm(base,          base + 2 * TILE_B, acc, lane, warp_m, warp_n);
        mma_block_ldsm(base + TILE_B, base + 3 * TILE_B, acc, lane, warp_m, warp_n);
    }

#pragma unroll
    for (int nt = 0; nt < 8; nt++) {
        const int col = blockCol + warp_n + nt * 8 + 2 * t;
        const float2 bv = *reinterpret_cast<const float2*>(&bias[col]);
#pragma unroll
        for (int mt = 0; mt < 2; mt++)
#pragma unroll
            for (int half = 0; half < 2; half++) {
                const int row = blockRow + warp_m + mt * 16 + half * 8 + g;
                if (row >= M) continue;
                float v0 = acc[mt][nt][half * 2 + 0] + bv.x;
                float v1 = acc[mt][nt][half * 2 + 1] + bv.y;
                if (relu) { v0 = fmaxf(v0, 0.f); v1 = fmaxf(v1, 0.f); }
                if (out_bf16) {
                    *(__nv_bfloat162*)((__nv_bfloat16*)Cv + (size_t)row * ldc + col) =
                        __float22bfloat162_rn(make_float2(v0, v1));
                } else {
                    *reinterpret_cast<float2*>((float*)Cv + (size_t)row * ldc + col) =
                        make_float2(v0, v1);
                }
            }
    }
}

// ===========================================================================
// fused_p2_segsum (proven R9): p2 BK=64 + deterministic segment sums.
// ===========================================================================
#define REDPAD 129
#define SMEM_P2 (2 * STAGE64)   // 81920 >= 128*129*4

__global__ __launch_bounds__(256)
void fused_p2_segsum(const __nv_bfloat16* __restrict__ h512,
                     const __nv_bfloat16* __restrict__ p2t,
                     const float* __restrict__ p2b,
                     float* __restrict__ part, int P, int group, int Bseg)
{
    extern __shared__ char smem[];
    const uint32_t smem_base = smem_u32(smem);
    float* red = (float*)smem;

    const int tid = threadIdx.x;
    const int wid = tid >> 5, lane = tid & 31;
    const int g = lane >> 2, t = lane & 3;
    const int warp_m = (wid & 3) * 32;
    const int warp_n = (wid >> 2) * 64;
    const int blockRow = blockIdx.x * 128;

    float acc[2][8][4];

    for (int nc = 0; nc < 2; nc++) {
#pragma unroll
        for (int mt = 0; mt < 2; mt++)
#pragma unroll
            for (int nt = 0; nt < 8; nt++)
#pragma unroll
                for (int i = 0; i < 4; i++) acc[mt][nt][i] = 0.0f;

        auto load_stage = [&](int it) {
            const uint32_t base = smem_base + (it & 1) * STAGE64;
            const int k0 = it * 64;
            load_tile(base,              h512, 512, blockRow, P,       k0,      tid);
            load_tile(base + TILE_B,     h512, 512, blockRow, P,       k0 + 32, tid);
            load_tile(base + 2 * TILE_B, p2t,  512, nc * 128, 1 << 30, k0,      tid);
            load_tile(base + 3 * TILE_B, p2t,  512, nc * 128, 1 << 30, k0 + 32, tid);
            CP_ASYNC_COMMIT();
        };

        load_stage(0);
        for (int it = 0; it < 8; it++) {          // K=512 -> 8 blocks of 64
            CP_ASYNC_WAIT0();
            __syncthreads();
            if (it + 1 < 8) load_stage(it + 1);
            const uint32_t base = smem_base + (it & 1) * STAGE64;
            mma_block_ldsm(base,          base + 2 * TILE_B, acc, lane, warp_m, warp_n);
            mma_block_ldsm(base + TILE_B, base + 3 * TILE_B, acc, lane, warp_m, warp_n);
        }
        __syncthreads();   // drain before red aliases the stages

#pragma unroll
        for (int nt = 0; nt < 8; nt++) {
            const int col = warp_n + nt * 8 + 2 * t;
            const float2 bv = *(const float2*)&p2b[nc * 128 + col];
#pragma unroll
            for (int mt = 0; mt < 2; mt++)
#pragma unroll
                for (int half = 0; half < 2; half++) {
                    const int row = warp_m + mt * 16 + half * 8 + g;
                    red[row * REDPAD + col]     = fmaxf(acc[mt][nt][half * 2 + 0] + bv.x, 0.f);
                    red[row * REDPAD + col + 1] = fmaxf(acc[mt][nt][half * 2 + 1] + bv.y, 0.f);
                }
        }
        __syncthreads();

        {
            const int col = tid & 127;
            const int rb  = (tid >> 7) * 64;
            float s = 0.f;
            bool any = false;
            int curseg = 0, nxt = 0;
            for (int r = rb; r < rb + 64; r++) {
                const int grow = blockRow + r;
                if (grow >= P) break;
                if (!any) {
                    curseg = grow / group;
                    nxt = (curseg + 1) * group;
                    any = true;
                } else if (grow >= nxt) {
                    const int slot = blockIdx.x - (curseg * group) / 128;
                    atomicAdd(&part[(size_t)slot * Bseg * 256 + curseg * 256 + nc * 128 + col], s);
                    s = 0.f;
                    curseg++;
                    nxt += group;
                }
                s += red[r * REDPAD + col];
            }
            if (any) {
                const int slot = blockIdx.x - (curseg * group) / 128;
                atomicAdd(&part[(size_t)slot * Bseg * 256 + curseg * 256 + nc * 128 + col], s);
            }
        }
        __syncthreads();
    }
}

// ===========================================================================
// prep_all (proven R9)
// ===========================================================================
#define AWT_SZ  (128 * 64)
#define BWT_SZ  (128 * 32)
#define P1T_SZ  (512 * 384)
#define P2T_SZ  (256 * 512)
#define P3T_SZ  (1024 * 256)
#define F1T_SZ  (512 * 1024)
#define ZERO_SZ (2 * B_MAX * 256)
#define PREP_TOTAL (AWT_SZ + BWT_SZ + P1T_SZ + P2T_SZ + P3T_SZ + F1T_SZ + ZERO_SZ)

__global__ void prep_all(const float* __restrict__ aw,  const float* __restrict__ bw,
                         const float* __restrict__ p1w, const float* __restrict__ p2w,
                         const float* __restrict__ p3w, const float* __restrict__ f1w,
                         __nv_bfloat16* __restrict__ wbf, float* __restrict__ part)
{
    int i = blockIdx.x * blockDim.x + threadIdx.x;
    if (i >= PREP_TOTAL) return;
    int off = 0;
    if (i < off + AWT_SZ) {
        int j = i - off; int n = j / 64, k = j % 64;
        wbf[i] = __float2bfloat16(aw[(size_t)k * 128 + n]); return;
    } off += AWT_SZ;
    if (i < off + BWT_SZ) {
        int j = i - off; int n = j / 32, k = j % 32;
        wbf[i] = __float2bfloat16(bw[(size_t)k * 128 + n]); return;
    } off += BWT_SZ;
    if (i < off + P1T_SZ) {
        int j = i - off; int n = j / 384, k = j % 384;
        wbf[i] = __float2bfloat16(p1w[(size_t)k * 512 + n]); return;
    } off += P1T_SZ;
    if (i < off + P2T_SZ) {
        int j = i - off; int n = j / 512, k = j % 512;
        wbf[i] = __float2bfloat16(p2w[(size_t)k * 256 + n]); return;
    } off += P2T_SZ;
    if (i < off + P3T_SZ) {
        int j = i - off; int n = j / 256, k = j % 256;
        wbf[i] = __float2bfloat16(p3w[(size_t)k * 1024 + n]); return;
    } off += P3T_SZ;
    if (i < off + F1T_SZ) {
        int j = i - off; int n = j / 1024, k = j % 1024;
        wbf[i] = __float2bfloat16(f1w[(size_t)k * 512 + n]); return;
    } off += F1T_SZ;
    part[i - off] = 0.0f;
}

// ---------------------------------------------------------------------------
__global__ void hm_combine(const float* __restrict__ part, const int* __restrict__ idx,
                           __nv_bfloat16* __restrict__ hm, int Bseg)
{
    int i = blockIdx.x * blockDim.x + threadIdx.x;
    if (i >= Bseg * 256) return;
    int s = i >> 8;
    hm[i] = __float2bfloat16((part[i] + part[(size_t)Bseg * 256 + i]) / (float)idx[s]);
}

// ---------------------------------------------------------------------------
// f2_final: fused  w = relu(z @ f2w + f2b);  out = w @ f3w + f3b
//   float4 z loads (k ascending within each lane's quarter, same order as
//   the scalar version: k = 4*q + {0,1,2,3} ... ). NOTE: to preserve exact
//   fp32 accumulation order we keep k strictly ascending: each float4 holds
//   k, k+1, k+2, k+3 and is consumed in that order.
// ---------------------------------------------------------------------------
__global__ __launch_bounds__(256, 2)
void f2_final(const float* __restrict__ z,
              const float* __restrict__ f2w, const float* __restrict__ f2b,
              const float* __restrict__ f3w, const float* __restrict__ f3b,
              float* __restrict__ out, int B)
{
    __shared__ float wsh[64][33];
    const int rloc = threadIdx.x >> 2;           // 0..63
    const int nq   = (threadIdx.x & 3) * 8;
    const int gm   = blockIdx.x * 64 + rloc;

    if (gm < B) {
        float acc[8] = {0,0,0,0,0,0,0,0};
        const float4* a4 = reinterpret_cast<const float4*>(z + (size_t)gm * 512);
        for (int k4 = 0; k4 < 128; k4++) {
            const float4 av = a4[k4];
            const float* wr = f2w + (size_t)(k4 * 4) * 32 + nq;
#pragma unroll
            for (int j = 0; j < 8; j++) acc[j] = fmaf(av.x, wr[j], acc[j]);
            wr += 32;
#pragma unroll
            for (int j = 0; j < 8; j++) acc[j] = fmaf(av.y, wr[j], acc[j]);
            wr += 32;
#pragma unroll
            for (int j = 0; j < 8; j++) acc[j] = fmaf(av.z, wr[j], acc[j]);
            wr += 32;
#pragma unroll
            for (int j = 0; j < 8; j++) acc[j] = fmaf(av.w, wr[j], acc[j]);
        }
#pragma unroll
        for (int j = 0; j < 8; j++)
            wsh[rloc][nq + j] = fmaxf(acc[j] + f2b[nq + j], 0.0f);
    }
    __syncthreads();

    if ((threadIdx.x & 3) == 0 && gm < B) {
        float s = 0.0f;
#pragma unroll
        for (int k = 0; k < 32; k++) s = fmaf(wsh[rloc][k], f3w[k], s);
        out[gm] = s + f3b[0];
    }
}

// ---------------------------------------------------------------------------
extern "C" void kernel_launch(void* const* d_in, const int* in_sizes, int n_in,
                              void* d_out, int out_size)
{
    const float* pairs     = (const float*)d_in[0];
    const int*   idx_pairs = (const int*)  d_in[1];
    const float* aw  = (const float*)d_in[3];
    const float* ab  = (const float*)d_in[4];
    const float* bw  = (const float*)d_in[5];
    const float* bb  = (const float*)d_in[6];
    const float* p1w = (const float*)d_in[7];
    const float* p1b = (const float*)d_in[8];
    const float* p2w = (const float*)d_in[9];
    const float* p2b = (const float*)d_in[10];
    const float* p3w = (const float*)d_in[11];
    const float* p3b = (const float*)d_in[12];
    const float* f1w = (const float*)d_in[13];
    const float* f1b = (const float*)d_in[14];
    const float* f2w = (const float*)d_in[15];
    const float* f2b = (const float*)d_in[16];
    const float* f3w = (const float*)d_in[17];
    const float* f3b = (const float*)d_in[18];
    float* out = (float*)d_out;

    const int P = in_sizes[0] / 160;
    const int B = in_sizes[1];
    const int group = P / B;

    cudaFuncSetAttribute(embed_all,       cudaFuncAttributeMaxDynamicSharedMemorySize, SMEM_EA);
    cudaFuncSetAttribute(tc_gemm_v2,      cudaFuncAttributeMaxDynamicSharedMemorySize, SMEM_V2);
    cudaFuncSetAttribute(fused_p2_segsum, cudaFuncAttributeMaxDynamicSharedMemorySize, SMEM_P2);

    __nv_bfloat16 *h384, *h512, *hm_bf, *y_bf, *wbf;
    float *part, *z;
    cudaGetSymbolAddress((void**)&h384,  g_h384);
    cudaGetSymbolAddress((void**)&h512,  g_h512);
    cudaGetSymbolAddress((void**)&part,  g_part);
    cudaGetSymbolAddress((void**)&hm_bf, g_hm_bf);
    cudaGetSymbolAddress((void**)&y_bf,  g_y_bf);
    cudaGetSymbolAddress((void**)&z,     g_z);
    cudaGetSymbolAddress((void**)&wbf,   g_wbf);

    __nv_bfloat16* awt = wbf;
    __nv_bfloat16* bwt = awt + AWT_SZ;
    __nv_bfloat16* p1t = bwt + BWT_SZ;
    __nv_bfloat16* p2t = p1t + P1T_SZ;
    __nv_bfloat16* p3t = p2t + P2T_SZ;
    __nv_bfloat16* f1t = p3t + P3T_SZ;

    prep_all<<<(PREP_TOTAL + 255) / 256, 256>>>(aw, bw, p1w, p2w, p3w, f1w, wbf, part);

    const int NT = (P + 127) / 128;

    embed_all<<<NT, 256, SMEM_EA>>>(pairs, awt, bwt, ab, bb, h384, P);
    tc_gemm_v2<<<dim3(NT, 4), 256, SMEM_V2>>>(h384, 384, p1t, p1b, h512, 512, P, 384, 1, 1);
    fused_p2_segsum<<<NT, 256, SMEM_P2>>>(h512, p2t, p2b, part, P, group, B);
    hm_combine<<<(B * 256 + 255) / 256, 256>>>(part, idx_pairs, hm_bf, B);

    const int BT = (B + 127) / 128;
    tc_gemm_v2<<<dim3(BT, 8), 256, SMEM_V2>>>(hm_bf, 256, p3t, p3b, y_bf, 1024, B, 256, 0, 1);
    tc_gemm_v2<<<dim3(BT, 4), 256, SMEM_V2>>>(y_bf, 1024, f1t, f1b, z, 512, B, 1024, 1, 0);
    f2_final<<<(B + 63) / 64, 256>>>(z, f2w, f2b, f3w, f3b, out, B);
}